// round 3
// baseline (speedup 1.0000x reference)
#include <cuda_runtime.h>

#define BSZ   4096
#define NNODE 16
#define OBSP  10
#define HID   128
#define GPB   4      // graphs per block (one warp each)
#define NTH   128

typedef unsigned long long ull;

// ---- packed f32x2 helpers (sm_103a; ptxas never auto-fuses these) ----
__device__ __forceinline__ ull pk2(float lo, float hi) {
    ull r; asm("mov.b64 %0, {%1, %2};" : "=l"(r) : "f"(lo), "f"(hi)); return r;
}
__device__ __forceinline__ void upk2(ull v, float& lo, float& hi) {
    asm("mov.b64 {%0, %1}, %2;" : "=f"(lo), "=f"(hi) : "l"(v));
}
__device__ __forceinline__ void ffma2(ull& d, ull a, ull b) {
    asm("fma.rn.f32x2 %0, %1, %2, %0;" : "+l"(d) : "l"(a), "l"(b));
}
__device__ __forceinline__ void add2(ull& d, ull a) {
    asm("add.rn.f32x2 %0, %0, %1;" : "+l"(d) : "l"(a));
}

struct __align__(16) GSh {
    float A[NNODE][NNODE];   // normalized adjacency (symmetric), 64B rows
    float Hs[HID][20];       // h0 transposed [col][row0..15], 80B stride
    float Xt[OBSP][NNODE];   // input features transposed
    float lx[NNODE], ly[NNODE], dinv[NNODE];
};

#define LOADROW8(dst, ptr) do { \
    const ulonglong2* _p = reinterpret_cast<const ulonglong2*>(ptr); \
    ulonglong2 _a = _p[0], _b = _p[1], _c = _p[2], _d = _p[3]; \
    dst[0]=_a.x; dst[1]=_a.y; dst[2]=_b.x; dst[3]=_b.y; \
    dst[4]=_c.x; dst[5]=_c.y; dst[6]=_d.x; dst[7]=_d.y; } while(0)

__global__ void __launch_bounds__(NTH, 4)
gcn_fused3(const float* __restrict__ obs, const float* __restrict__ act,
           const float* __restrict__ Q1W0, const float* __restrict__ Q1b0,
           const float* __restrict__ Q1W1, const float* __restrict__ Q1b1,
           const float* __restrict__ Q1W2, const float* __restrict__ Q1b2,
           const float* __restrict__ Q2W0, const float* __restrict__ Q2b0,
           const float* __restrict__ Q2W1, const float* __restrict__ Q2b1,
           const float* __restrict__ Q2W2, const float* __restrict__ Q2b2,
           float* __restrict__ out)
{
    __shared__ GSh sh[GPB];
    const int warp = threadIdx.x >> 5;
    const int lane = threadIdx.x & 31;
    GSh& S = sh[warp];
    const int g = blockIdx.x * GPB + warp;   // one warp == one graph

    // ---- features: loc = obs cols 0,1; x = obs cols 2..9 ++ action cols 0,1
    {
        const float* ob = obs + (size_t)g * (NNODE * OBSP);
        #pragma unroll
        for (int r = 0; r < 5; r++) {
            int idx = lane + 32 * r;
            float v = ob[idx];
            int n = idx / OBSP, k = idx - n * OBSP;
            if (k == 0)      S.lx[n] = v;
            else if (k == 1) S.ly[n] = v;
            else             S.Xt[k - 2][n] = v;
        }
        float v = act[(size_t)g * (NNODE * 2) + lane];
        S.Xt[8 + (lane & 1)][lane >> 1] = v;
    }
    __syncwarp();

    // ---- adjacency w_ij = exp(-||loc_i - loc_j||); bitwise-symmetric
    #pragma unroll
    for (int r = 0; r < 8; r++) {
        int e = lane * 8 + r, i = e >> 4, j = e & 15;
        float dx = S.lx[i] - S.lx[j], dy = S.ly[i] - S.ly[j];
        S.A[i][j] = expf(-sqrtf(dx * dx + dy * dy));
    }
    __syncwarp();
    if (lane < NNODE) {
        float s = 0.f;
        #pragma unroll
        for (int j = 0; j < NNODE; j++) s += S.A[j][lane];  // symmetric: col == row
        S.dinv[lane] = rsqrtf(s);                           // deg >= 1 (self loop)
    }
    __syncwarp();
    #pragma unroll
    for (int r = 0; r < 8; r++) {
        int e = lane * 8 + r, i = e >> 4, j = e & 15;
        S.A[i][j] *= S.dinv[i] * S.dinv[j];
    }
    __syncwarp();

    const float* W0a[2] = {Q1W0, Q2W0};  const float* B0a[2] = {Q1b0, Q2b0};
    const float* W1a[2] = {Q1W1, Q2W1};  const float* B1a[2] = {Q1b1, Q2b1};
    const float* W2a[2] = {Q1W2, Q2W2};  const float* B2a[2] = {Q1b2, Q2b2};

    #pragma unroll
    for (int q = 0; q < 2; q++) {
        // Thread owns hidden columns 4*lane + {0,1,2,3}.
        // acc[c*8+m] = packed rows (2m,2m+1) of y for column 4*lane+c.
        ull acc[32];
        #pragma unroll
        for (int p = 0; p < 32; p++) acc[p] = 0ull;

        // ---- layer 0 GEMM: y0 = X @ W0 (k = 0..9); one LDG.128 per k
        #pragma unroll
        for (int k = 0; k < OBSP; k++) {
            float4 w4 = __ldg(reinterpret_cast<const float4*>(W0a[q] + k * HID) + lane);
            ull row[8]; LOADROW8(row, S.Xt[k]);
            ull wd;
            wd = pk2(w4.x, w4.x);
            #pragma unroll
            for (int m = 0; m < 8; m++) ffma2(acc[m],      row[m], wd);
            wd = pk2(w4.y, w4.y);
            #pragma unroll
            for (int m = 0; m < 8; m++) ffma2(acc[8 + m],  row[m], wd);
            wd = pk2(w4.z, w4.z);
            #pragma unroll
            for (int m = 0; m < 8; m++) ffma2(acc[16 + m], row[m], wd);
            wd = pk2(w4.w, w4.w);
            #pragma unroll
            for (int m = 0; m < 8; m++) ffma2(acc[24 + m], row[m], wd);
        }

        // ---- agg0 = A @ y0, +b0, relu -> Hs. ONE column per pass (regs!).
        {
            float4 b0 = __ldg(reinterpret_cast<const float4*>(B0a[q]) + lane);
            float bc[4] = {b0.x, b0.y, b0.z, b0.w};
            #pragma unroll
            for (int c = 0; c < 4; c++) {
                ull agg[8];
                #pragma unroll
                for (int m = 0; m < 8; m++) agg[m] = 0ull;
                #pragma unroll
                for (int jp = 0; jp < 8; jp++) {
                    float lo, hi; upk2(acc[c * 8 + jp], lo, hi);
                    ull ar[8];
                    LOADROW8(ar, S.A[2 * jp]);       // row j == col j (symmetric)
                    ull yd = pk2(lo, lo);
                    #pragma unroll
                    for (int m = 0; m < 8; m++) ffma2(agg[m], ar[m], yd);
                    LOADROW8(ar, S.A[2 * jp + 1]);
                    yd = pk2(hi, hi);
                    #pragma unroll
                    for (int m = 0; m < 8; m++) ffma2(agg[m], ar[m], yd);
                }
                int col = 4 * lane + c;
                float b = bc[c];
                float h[16];
                #pragma unroll
                for (int m = 0; m < 8; m++) {
                    float lo, hi; upk2(agg[m], lo, hi);
                    h[2 * m]     = fmaxf(lo + b, 0.f);
                    h[2 * m + 1] = fmaxf(hi + b, 0.f);
                }
                float4* dst = reinterpret_cast<float4*>(&S.Hs[col][0]);
                dst[0] = make_float4(h[0],  h[1],  h[2],  h[3]);
                dst[1] = make_float4(h[4],  h[5],  h[6],  h[7]);
                dst[2] = make_float4(h[8],  h[9],  h[10], h[11]);
                dst[3] = make_float4(h[12], h[13], h[14], h[15]);
            }
        }
        __syncwarp();

        // ---- layer 1 GEMM (dominant): y1 = h0 @ W1, k = 0..127
        #pragma unroll
        for (int p = 0; p < 32; p++) acc[p] = 0ull;
        {
            const float4* W1v = reinterpret_cast<const float4*>(W1a[q]) + lane;
            #pragma unroll 4
            for (int k = 0; k < HID; k++) {
                float4 w4 = __ldg(W1v + k * (HID / 4));
                ull row[8]; LOADROW8(row, S.Hs[k]);   // broadcast, 80B stride
                ull wd;
                wd = pk2(w4.x, w4.x);
                #pragma unroll
                for (int m = 0; m < 8; m++) ffma2(acc[m],      row[m], wd);
                wd = pk2(w4.y, w4.y);
                #pragma unroll
                for (int m = 0; m < 8; m++) ffma2(acc[8 + m],  row[m], wd);
                wd = pk2(w4.z, w4.z);
                #pragma unroll
                for (int m = 0; m < 8; m++) ffma2(acc[16 + m], row[m], wd);
                wd = pk2(w4.w, w4.w);
                #pragma unroll
                for (int m = 0; m < 8; m++) ffma2(acc[24 + m], row[m], wd);
            }
        }
        __syncwarp();   // all lanes done reading Hs before next head rewrites it

        // ---- agg1 = A @ y1, +b1, relu, fused layer-2 partial: part += h1 * W2[col]
        ull part[8];
        #pragma unroll
        for (int m = 0; m < 8; m++) part[m] = 0ull;
        {
            float4 b1 = __ldg(reinterpret_cast<const float4*>(B1a[q]) + lane);
            float4 w2 = __ldg(reinterpret_cast<const float4*>(W2a[q]) + lane);
            float bc[4] = {b1.x, b1.y, b1.z, b1.w};
            float wc[4] = {w2.x, w2.y, w2.z, w2.w};
            #pragma unroll
            for (int c = 0; c < 4; c++) {
                ull agg[8];
                #pragma unroll
                for (int m = 0; m < 8; m++) agg[m] = 0ull;
                #pragma unroll
                for (int jp = 0; jp < 8; jp++) {
                    float lo, hi; upk2(acc[c * 8 + jp], lo, hi);
                    ull ar[8];
                    LOADROW8(ar, S.A[2 * jp]);
                    ull yd = pk2(lo, lo);
                    #pragma unroll
                    for (int m = 0; m < 8; m++) ffma2(agg[m], ar[m], yd);
                    LOADROW8(ar, S.A[2 * jp + 1]);
                    yd = pk2(hi, hi);
                    #pragma unroll
                    for (int m = 0; m < 8; m++) ffma2(agg[m], ar[m], yd);
                }
                float b = bc[c];
                ull w2d = pk2(wc[c], wc[c]);
                #pragma unroll
                for (int m = 0; m < 8; m++) {
                    float lo, hi; upk2(agg[m], lo, hi);
                    lo = fmaxf(lo + b, 0.f);
                    hi = fmaxf(hi + b, 0.f);
                    ffma2(part[m], pk2(lo, hi), w2d);
                }
            }
        }

        // ---- warp-reduce part (sum over all 128 hidden cols)
        #pragma unroll
        for (int off = 16; off > 0; off >>= 1) {
            #pragma unroll
            for (int m = 0; m < 8; m++) {
                ull o = __shfl_xor_sync(0xffffffffu, part[m], off);
                add2(part[m], o);
            }
        }

        // ---- final agg: out[i] = b2 + sum_j A[i][j] * y2[j]
        if (lane < NNODE) {
            float y2[16];
            #pragma unroll
            for (int m = 0; m < 8; m++) upk2(part[m], y2[2 * m], y2[2 * m + 1]);
            float o = __ldg(B2a[q]);
            #pragma unroll
            for (int j = 0; j < NNODE; j++)
                o = fmaf(S.A[j][lane], y2[j], o);   // conflict-free
            out[(size_t)q * BSZ * NNODE + (size_t)g * NNODE + lane] = o;
        }
        __syncwarp();
    }
}

extern "C" void kernel_launch(void* const* d_in, const int* in_sizes, int n_in,
                              void* d_out, int out_size)
{
    (void)in_sizes; (void)n_in; (void)out_size;
    gcn_fused3<<<BSZ / GPB, NTH>>>(
        (const float*)d_in[0],  (const float*)d_in[1],
        (const float*)d_in[2],  (const float*)d_in[3],
        (const float*)d_in[4],  (const float*)d_in[5],
        (const float*)d_in[6],  (const float*)d_in[7],
        (const float*)d_in[8],  (const float*)d_in[9],
        (const float*)d_in[10], (const float*)d_in[11],
        (const float*)d_in[12], (const float*)d_in[13],
        (float*)d_out);
}

// round 4
// speedup vs baseline: 1.4259x; 1.4259x over previous
#include <cuda_runtime.h>

#define BSZ   4096
#define NNODE 16
#define OBSP  10
#define HID   128
#define GPB   4      // graphs per block (one warp each)
#define NTH   128

typedef unsigned long long ull;

// ---- packed f32x2 helpers (sm_103a; ptxas never auto-fuses these) ----
__device__ __forceinline__ ull pk2(float lo, float hi) {
    ull r; asm("mov.b64 %0, {%1, %2};" : "=l"(r) : "f"(lo), "f"(hi)); return r;
}
__device__ __forceinline__ void upk2(ull v, float& lo, float& hi) {
    asm("mov.b64 {%0, %1}, %2;" : "=f"(lo), "=f"(hi) : "l"(v));
}
__device__ __forceinline__ void ffma2(ull& d, ull a, ull b) {
    asm("fma.rn.f32x2 %0, %1, %2, %0;" : "+l"(d) : "l"(a), "l"(b));
}

// Per-graph shared state: 2992 floats = 11968 B; x4 graphs = 47872 B (<48K static)
struct __align__(16) GSh {
    float A[NNODE][NNODE];     // normalized adjacency (symmetric)
    float Xat[OBSP][NNODE];    // (A@X) transposed: Xat[k][i]
    float y2s[NNODE];
    float HsY[HID * 20];       // union: h0 transposed Hs[col][row] (stride 20)
                               //        y1 row-major  Ys[row][col] (stride 132)
                               //        scratch: Xt[10][16], lx, ly, dinv
};

#define LOADROW8(dst, ptr) do { \
    const ulonglong2* _p = reinterpret_cast<const ulonglong2*>(ptr); \
    ulonglong2 _a = _p[0], _b = _p[1], _c = _p[2], _d = _p[3]; \
    dst[0]=_a.x; dst[1]=_a.y; dst[2]=_b.x; dst[3]=_b.y; \
    dst[4]=_c.x; dst[5]=_c.y; dst[6]=_d.x; dst[7]=_d.y; } while(0)

__global__ void __launch_bounds__(NTH, 4)
gcn_fused4(const float* __restrict__ obs, const float* __restrict__ act,
           const float* __restrict__ Q1W0, const float* __restrict__ Q1b0,
           const float* __restrict__ Q1W1, const float* __restrict__ Q1b1,
           const float* __restrict__ Q1W2, const float* __restrict__ Q1b2,
           const float* __restrict__ Q2W0, const float* __restrict__ Q2b0,
           const float* __restrict__ Q2W1, const float* __restrict__ Q2b1,
           const float* __restrict__ Q2W2, const float* __restrict__ Q2b2,
           float* __restrict__ out)
{
    __shared__ GSh sh[GPB];
    const int warp = threadIdx.x >> 5;
    const int lane = threadIdx.x & 31;
    GSh& S = sh[warp];
    const int g = blockIdx.x * GPB + warp;   // one warp == one graph

    // scratch aliases inside HsY (dead before any HsY use)
    float* Xt   = S.HsY;            // [10][16]
    float* lx   = S.HsY + 160;
    float* ly   = S.HsY + 176;
    float* dinv = S.HsY + 192;

    // ---- features: loc = obs cols 0,1; x = obs cols 2..9 ++ action cols 0,1
    {
        const float* ob = obs + (size_t)g * (NNODE * OBSP);
        #pragma unroll
        for (int r = 0; r < 5; r++) {
            int idx = lane + 32 * r;
            float v = ob[idx];
            int n = idx / OBSP, k = idx - n * OBSP;
            if (k == 0)      lx[n] = v;
            else if (k == 1) ly[n] = v;
            else             Xt[(k - 2) * NNODE + n] = v;
        }
        float v = act[(size_t)g * (NNODE * 2) + lane];
        Xt[(8 + (lane & 1)) * NNODE + (lane >> 1)] = v;
    }
    __syncwarp();

    // ---- adjacency w_ij = exp(-||loc_i - loc_j||); bitwise-symmetric
    #pragma unroll
    for (int r = 0; r < 8; r++) {
        int e = lane * 8 + r, i = e >> 4, j = e & 15;
        float dx = lx[i] - lx[j], dy = ly[i] - ly[j];
        S.A[i][j] = expf(-sqrtf(dx * dx + dy * dy));
    }
    __syncwarp();
    if (lane < NNODE) {
        float s = 0.f;
        #pragma unroll
        for (int j = 0; j < NNODE; j++) s += S.A[j][lane];
        dinv[lane] = rsqrtf(s);                 // deg >= 1 (self loop)
    }
    __syncwarp();
    #pragma unroll
    for (int r = 0; r < 8; r++) {
        int e = lane * 8 + r, i = e >> 4, j = e & 15;
        S.A[i][j] *= dinv[i] * dinv[j];
    }
    __syncwarp();

    // ---- Xa = A @ X (shared by both heads), stored transposed Xat[k][i]
    #pragma unroll
    for (int r = 0; r < 5; r++) {
        int idx = lane + 32 * r;        // 160 = 16 x 10 outputs
        int i = idx / OBSP, k = idx - i * OBSP;
        float s = 0.f;
        #pragma unroll
        for (int j = 0; j < NNODE; j++) s = fmaf(S.A[i][j], Xt[k * NNODE + j], s);
        S.Xat[k][i] = s;
    }
    __syncwarp();

    for (int q = 0; q < 2; q++) {
        const float* W0 = q ? Q2W0 : Q1W0;
        const float* B0 = q ? Q2b0 : Q1b0;
        const float* W1 = q ? Q2W1 : Q1W1;
        const float* B1 = q ? Q2b1 : Q1b1;
        const float* W2 = q ? Q2W2 : Q1W2;
        const float* B2 = q ? Q2b2 : Q1b2;

        // thread owns cols 4*lane+{0..3}; acc[c*8+m] = rows(2m,2m+1) of col
        ull acc[32];
        #pragma unroll
        for (int p = 0; p < 32; p++) acc[p] = 0ull;

        // ---- GEMM0 (pre-aggregated): h0 = relu(Xa @ W0 + b0)
        #pragma unroll
        for (int k = 0; k < OBSP; k++) {
            float4 w4 = __ldg(reinterpret_cast<const float4*>(W0 + k * HID) + lane);
            ull row[8]; LOADROW8(row, &S.Xat[k][0]);
            ull wd;
            wd = pk2(w4.x, w4.x);
            #pragma unroll
            for (int m = 0; m < 8; m++) ffma2(acc[m],      row[m], wd);
            wd = pk2(w4.y, w4.y);
            #pragma unroll
            for (int m = 0; m < 8; m++) ffma2(acc[8 + m],  row[m], wd);
            wd = pk2(w4.z, w4.z);
            #pragma unroll
            for (int m = 0; m < 8; m++) ffma2(acc[16 + m], row[m], wd);
            wd = pk2(w4.w, w4.w);
            #pragma unroll
            for (int m = 0; m < 8; m++) ffma2(acc[24 + m], row[m], wd);
        }
        __syncwarp();   // scratch (q==0) / Ys (q==1) reads done before Hs writes
        {
            float4 b0 = __ldg(reinterpret_cast<const float4*>(B0) + lane);
            float bc[4] = {b0.x, b0.y, b0.z, b0.w};
            #pragma unroll
            for (int c = 0; c < 4; c++) {
                int col = 4 * lane + c;
                float4* dst = reinterpret_cast<float4*>(&S.HsY[col * 20]);
                #pragma unroll
                for (int u = 0; u < 4; u++) {
                    float h0_, h1_, h2_, h3_;
                    upk2(acc[c * 8 + 2 * u],     h0_, h1_);
                    upk2(acc[c * 8 + 2 * u + 1], h2_, h3_);
                    dst[u] = make_float4(fmaxf(h0_ + bc[c], 0.f), fmaxf(h1_ + bc[c], 0.f),
                                         fmaxf(h2_ + bc[c], 0.f), fmaxf(h3_ + bc[c], 0.f));
                }
            }
        }
        __syncwarp();

        // ---- GEMM1 (dominant): y1 = h0 @ W1
        #pragma unroll
        for (int p = 0; p < 32; p++) acc[p] = 0ull;
        {
            const float4* W1v = reinterpret_cast<const float4*>(W1) + lane;
            #pragma unroll 4
            for (int k = 0; k < HID; k++) {
                float4 w4 = __ldg(W1v + k * (HID / 4));
                ull row[8]; LOADROW8(row, &S.HsY[k * 20]);   // broadcast
                ull wd;
                wd = pk2(w4.x, w4.x);
                #pragma unroll
                for (int m = 0; m < 8; m++) ffma2(acc[m],      row[m], wd);
                wd = pk2(w4.y, w4.y);
                #pragma unroll
                for (int m = 0; m < 8; m++) ffma2(acc[8 + m],  row[m], wd);
                wd = pk2(w4.z, w4.z);
                #pragma unroll
                for (int m = 0; m < 8; m++) ffma2(acc[16 + m], row[m], wd);
                wd = pk2(w4.w, w4.w);
                #pragma unroll
                for (int m = 0; m < 8; m++) ffma2(acc[24 + m], row[m], wd);
            }
        }
        __syncwarp();   // all lanes finished reading h0 before aliasing writes

        // ---- spill y1 to smem row-major (aliases dead h0): Ys[row][col], stride 132
        #pragma unroll
        for (int m = 0; m < 8; m++) {
            float a0, a1, b0_, b1_, c0, c1, d0, d1;
            upk2(acc[m],      a0, a1);
            upk2(acc[8 + m],  b0_, b1_);
            upk2(acc[16 + m], c0, c1);
            upk2(acc[24 + m], d0, d1);
            *reinterpret_cast<float4*>(&S.HsY[(2 * m) * 132 + 4 * lane])
                = make_float4(a0, b0_, c0, d0);
            *reinterpret_cast<float4*>(&S.HsY[(2 * m + 1) * 132 + 4 * lane])
                = make_float4(a1, b1_, c1, d1);
        }
        __syncwarp();

        // ---- agg1 = A @ y1 (row-parallel): lane -> (i = lane&15, half = lane>>4)
        const int i = lane & 15, half = lane >> 4;
        ull acc2[32];
        #pragma unroll
        for (int p = 0; p < 32; p++) acc2[p] = 0ull;
        #pragma unroll 4
        for (int j = 0; j < NNODE; j++) {
            float a = S.A[j][i];                 // symmetric; contiguous broadcast
            ull ad = pk2(a, a);
            const ulonglong2* yrow =
                reinterpret_cast<const ulonglong2*>(&S.HsY[j * 132 + 64 * half]);
            #pragma unroll
            for (int c4 = 0; c4 < 16; c4++) {
                ulonglong2 y4 = yrow[c4];        // LDS.128, 2 addrs -> 2x bcast
                ffma2(acc2[2 * c4],     y4.x, ad);
                ffma2(acc2[2 * c4 + 1], y4.y, ad);
            }
        }

        // ---- h1 = relu(acc2 + b1); part = sum over cols of h1 * W2
        float part = 0.f;
        {
            const float4* B1v = reinterpret_cast<const float4*>(B1) + 16 * half;
            const float4* W2v = reinterpret_cast<const float4*>(W2) + 16 * half;
            #pragma unroll
            for (int c4 = 0; c4 < 16; c4++) {
                float4 bv = __ldg(B1v + c4);
                float4 wv = __ldg(W2v + c4);
                float h0_, h1_, h2_, h3_;
                upk2(acc2[2 * c4],     h0_, h1_);
                upk2(acc2[2 * c4 + 1], h2_, h3_);
                part = fmaf(fmaxf(h0_ + bv.x, 0.f), wv.x, part);
                part = fmaf(fmaxf(h1_ + bv.y, 0.f), wv.y, part);
                part = fmaf(fmaxf(h2_ + bv.z, 0.f), wv.z, part);
                part = fmaf(fmaxf(h3_ + bv.w, 0.f), wv.w, part);
            }
        }
        part += __shfl_xor_sync(0xffffffffu, part, 16);   // combine halves (same i)
        if (lane < NNODE) S.y2s[lane] = part;
        __syncwarp();

        // ---- out[i] = b2 + sum_j A[i][j] * y2[j]
        if (lane < NNODE) {
            float o = __ldg(B2);
            #pragma unroll
            for (int j = 0; j < NNODE; j++)
                o = fmaf(S.A[j][lane], S.y2s[j], o);
            out[(size_t)q * BSZ * NNODE + (size_t)g * NNODE + lane] = o;
        }
        __syncwarp();   // before next head overwrites HsY / y2s
    }
}

extern "C" void kernel_launch(void* const* d_in, const int* in_sizes, int n_in,
                              void* d_out, int out_size)
{
    (void)in_sizes; (void)n_in; (void)out_size;
    gcn_fused4<<<BSZ / GPB, NTH>>>(
        (const float*)d_in[0],  (const float*)d_in[1],
        (const float*)d_in[2],  (const float*)d_in[3],
        (const float*)d_in[4],  (const float*)d_in[5],
        (const float*)d_in[6],  (const float*)d_in[7],
        (const float*)d_in[8],  (const float*)d_in[9],
        (const float*)d_in[10], (const float*)d_in[11],
        (const float*)d_in[12], (const float*)d_in[13],
        (float*)d_out);
}

// round 5
// speedup vs baseline: 1.6530x; 1.1593x over previous
#include <cuda_runtime.h>

#define BSZ   4096
#define NNODE 16
#define OBSP  10
#define HID   128
#define GPB   4      // graphs per block (one warp each)
#define NTH   128

typedef unsigned long long ull;

// ---- packed f32x2 helpers (sm_103a; ptxas never auto-fuses these) ----
__device__ __forceinline__ ull pk2(float lo, float hi) {
    ull r; asm("mov.b64 %0, {%1, %2};" : "=l"(r) : "f"(lo), "f"(hi)); return r;
}
__device__ __forceinline__ void upk2(ull v, float& lo, float& hi) {
    asm("mov.b64 {%0, %1}, %2;" : "=f"(lo), "=f"(hi) : "l"(v));
}
__device__ __forceinline__ void ffma2(ull& d, ull a, ull b) {
    asm("fma.rn.f32x2 %0, %1, %2, %0;" : "+l"(d) : "l"(a), "l"(b));
}
__device__ __forceinline__ void add2(ull& d, ull a) {
    asm("add.rn.f32x2 %0, %0, %1;" : "+l"(d) : "l"(a));
}

// Per-graph shared: 2464 floats = 9856 B; x4 graphs = 39424 B (<48K static,
// 4 CTAs/SM = 157.7KB smem -> 164KB carveout tier -> 64KB L1D for W1 residency)
struct __align__(16) GSh {
    float A[NNODE][NNODE];   // normalized adjacency (symmetric)
    float Xat[OBSP][NNODE];  // (A@X) transposed
    float HsY[HID * 16];     // union:
                             //  Hs: col-major h0, col c at [c*16..c*16+16),
                             //      16B-unit u stored at slot (u+(c>>2))&3
                             //  Ys: y1 row-major [j*128 + col]
                             //  scratch: Xt[10][16], lx, ly, dinv
};

#define LOADROW8(dst, ptr) do { \
    const ulonglong2* _p = reinterpret_cast<const ulonglong2*>(ptr); \
    ulonglong2 _a = _p[0], _b = _p[1], _c = _p[2], _d = _p[3]; \
    dst[0]=_a.x; dst[1]=_a.y; dst[2]=_b.x; dst[3]=_b.y; \
    dst[4]=_c.x; dst[5]=_c.y; dst[6]=_d.x; dst[7]=_d.y; } while(0)

__global__ void __launch_bounds__(NTH, 4)
gcn_fused5(const float* __restrict__ obs, const float* __restrict__ act,
           const float* __restrict__ Q1W0, const float* __restrict__ Q1b0,
           const float* __restrict__ Q1W1, const float* __restrict__ Q1b1,
           const float* __restrict__ Q1W2, const float* __restrict__ Q1b2,
           const float* __restrict__ Q2W0, const float* __restrict__ Q2b0,
           const float* __restrict__ Q2W1, const float* __restrict__ Q2b1,
           const float* __restrict__ Q2W2, const float* __restrict__ Q2b2,
           float* __restrict__ out)
{
    __shared__ GSh sh[GPB];
    const int warp = threadIdx.x >> 5;
    const int lane = threadIdx.x & 31;
    GSh& S = sh[warp];
    const int g = blockIdx.x * GPB + warp;   // one warp == one graph

    // scratch aliases inside HsY (dead before any HsY use)
    float* Xt   = S.HsY;            // [10][16]
    float* lx   = S.HsY + 160;
    float* ly   = S.HsY + 176;
    float* dinv = S.HsY + 192;

    // ---- features: loc = obs cols 0,1; x = obs cols 2..9 ++ action cols 0,1
    {
        const float* ob = obs + (size_t)g * (NNODE * OBSP);
        #pragma unroll
        for (int r = 0; r < 5; r++) {
            int idx = lane + 32 * r;
            float v = ob[idx];
            int n = idx / OBSP, k = idx - n * OBSP;
            if (k == 0)      lx[n] = v;
            else if (k == 1) ly[n] = v;
            else             Xt[(k - 2) * NNODE + n] = v;
        }
        float v = act[(size_t)g * (NNODE * 2) + lane];
        Xt[(8 + (lane & 1)) * NNODE + (lane >> 1)] = v;
    }
    __syncwarp();

    // ---- adjacency w_ij = exp(-||loc_i - loc_j||); bitwise-symmetric
    #pragma unroll
    for (int r = 0; r < 8; r++) {
        int e = lane * 8 + r, i = e >> 4, j = e & 15;
        float dx = lx[i] - lx[j], dy = ly[i] - ly[j];
        S.A[i][j] = expf(-sqrtf(dx * dx + dy * dy));
    }
    __syncwarp();
    if (lane < NNODE) {
        float s = 0.f;
        #pragma unroll
        for (int j = 0; j < NNODE; j++) s += S.A[j][lane];
        dinv[lane] = rsqrtf(s);                 // deg >= 1 (self loop)
    }
    __syncwarp();
    #pragma unroll
    for (int r = 0; r < 8; r++) {
        int e = lane * 8 + r, i = e >> 4, j = e & 15;
        S.A[i][j] *= dinv[i] * dinv[j];
    }
    __syncwarp();

    // ---- Xa = A @ X (shared by both heads), stored transposed Xat[k][i]
    #pragma unroll
    for (int r = 0; r < 5; r++) {
        int idx = lane + 32 * r;        // 160 = 16 x 10 outputs
        int i = idx / OBSP, k = idx - i * OBSP;
        float s = 0.f;
        #pragma unroll
        for (int j = 0; j < NNODE; j++) s = fmaf(S.A[i][j], Xt[k * NNODE + j], s);
        S.Xat[k][i] = s;
    }
    __syncwarp();

    for (int q = 0; q < 2; q++) {
        const float* W0 = q ? Q2W0 : Q1W0;
        const float* B0 = q ? Q2b0 : Q1b0;
        const float* W1 = q ? Q2W1 : Q1W1;
        const float* B1 = q ? Q2b1 : Q1b1;
        const float* W2 = q ? Q2W2 : Q1W2;
        const float* B2 = q ? Q2b2 : Q1b2;

        // thread owns cols 4*lane+{0..3}; acc[c*8+m] = rows(2m,2m+1) of col
        ull acc[32];
        #pragma unroll
        for (int p = 0; p < 32; p++) acc[p] = 0ull;

        // ---- GEMM0 (pre-aggregated): h0 = relu(Xa @ W0 + b0)
        #pragma unroll
        for (int k = 0; k < OBSP; k++) {
            float4 w4 = __ldg(reinterpret_cast<const float4*>(W0 + k * HID) + lane);
            ull row[8]; LOADROW8(row, &S.Xat[k][0]);
            ull wd;
            wd = pk2(w4.x, w4.x);
            #pragma unroll
            for (int m = 0; m < 8; m++) ffma2(acc[m],      row[m], wd);
            wd = pk2(w4.y, w4.y);
            #pragma unroll
            for (int m = 0; m < 8; m++) ffma2(acc[8 + m],  row[m], wd);
            wd = pk2(w4.z, w4.z);
            #pragma unroll
            for (int m = 0; m < 8; m++) ffma2(acc[16 + m], row[m], wd);
            wd = pk2(w4.w, w4.w);
            #pragma unroll
            for (int m = 0; m < 8; m++) ffma2(acc[24 + m], row[m], wd);
        }
        __syncwarp();   // prior-phase HsY reads done before Hs writes
        {
            float4 b0v = __ldg(reinterpret_cast<const float4*>(B0) + lane);
            float bc[4] = {b0v.x, b0v.y, b0v.z, b0v.w};
            const int rw = lane & 3;         // = (col>>2)&3 for col=4*lane+c
            #pragma unroll
            for (int c = 0; c < 4; c++) {
                float4* dst = reinterpret_cast<float4*>(&S.HsY[(4 * lane + c) * 16]);
                #pragma unroll
                for (int u = 0; u < 4; u++) {
                    float h0_, h1_, h2_, h3_;
                    upk2(acc[c * 8 + 2 * u],     h0_, h1_);
                    upk2(acc[c * 8 + 2 * u + 1], h2_, h3_);
                    dst[(u + rw) & 3] =
                        make_float4(fmaxf(h0_ + bc[c], 0.f), fmaxf(h1_ + bc[c], 0.f),
                                    fmaxf(h2_ + bc[c], 0.f), fmaxf(h3_ + bc[c], 0.f));
                }
            }
        }
        __syncwarp();

        // ---- GEMM1 (dominant): y1 = h0 @ W1; k unrolled by 16 so the
        //      swizzle rotation r=(s>>2)&3 is compile-time per slot.
        #pragma unroll
        for (int p = 0; p < 32; p++) acc[p] = 0ull;
        {
            const float4* W1v = reinterpret_cast<const float4*>(W1) + lane;
            #pragma unroll 1
            for (int kb = 0; kb < HID; kb += 16) {
                #pragma unroll
                for (int s = 0; s < 16; s++) {
                    const int k = kb + s;
                    const int r = (s >> 2) & 3;          // compile-time
                    float4 w4 = __ldg(W1v + k * (HID / 4));
                    const ulonglong2* unit =
                        reinterpret_cast<const ulonglong2*>(&S.HsY[k * 16]);
                    ulonglong2 d0 = unit[(0 + r) & 3];
                    ulonglong2 d1 = unit[(1 + r) & 3];
                    ulonglong2 d2 = unit[(2 + r) & 3];
                    ulonglong2 d3 = unit[(3 + r) & 3];
                    ull row[8] = {d0.x, d0.y, d1.x, d1.y, d2.x, d2.y, d3.x, d3.y};
                    ull wd;
                    wd = pk2(w4.x, w4.x);
                    #pragma unroll
                    for (int m = 0; m < 8; m++) ffma2(acc[m],      row[m], wd);
                    wd = pk2(w4.y, w4.y);
                    #pragma unroll
                    for (int m = 0; m < 8; m++) ffma2(acc[8 + m],  row[m], wd);
                    wd = pk2(w4.z, w4.z);
                    #pragma unroll
                    for (int m = 0; m < 8; m++) ffma2(acc[16 + m], row[m], wd);
                    wd = pk2(w4.w, w4.w);
                    #pragma unroll
                    for (int m = 0; m < 8; m++) ffma2(acc[24 + m], row[m], wd);
                }
            }
        }
        __syncwarp();   // all lanes finished reading h0 before aliasing writes

        // ---- spill y1 row-major (aliases dead h0): Ys[j][col], stride 128
        #pragma unroll
        for (int m = 0; m < 8; m++) {
            float a0, a1, b0_, b1_, c0, c1, d0, d1;
            upk2(acc[m],      a0, a1);
            upk2(acc[8 + m],  b0_, b1_);
            upk2(acc[16 + m], c0, c1);
            upk2(acc[24 + m], d0, d1);
            *reinterpret_cast<float4*>(&S.HsY[(2 * m) * HID + 4 * lane])
                = make_float4(a0, b0_, c0, d0);
            *reinterpret_cast<float4*>(&S.HsY[(2 * m + 1) * HID + 4 * lane])
                = make_float4(a1, b1_, c1, d1);
        }
        // (agg1 reads only this lane's own Ys slice -> program order suffices)

        // ---- agg1 = A @ y1; lane owns cols 4*lane+{0..3} for ALL 16 rows.
        //      acc2[c*8+m] = out rows(2m,2m+1) of col 4*lane+c
        ull acc2[32];
        #pragma unroll
        for (int p = 0; p < 32; p++) acc2[p] = 0ull;
        #pragma unroll 4
        for (int j = 0; j < NNODE; j++) {
            float4 y4 = *reinterpret_cast<const float4*>(&S.HsY[j * HID + 4 * lane]);
            ull ar[8]; LOADROW8(ar, &S.A[j][0]);   // col j of A (symmetric), bcast
            ull yd;
            yd = pk2(y4.x, y4.x);
            #pragma unroll
            for (int m = 0; m < 8; m++) ffma2(acc2[m],      ar[m], yd);
            yd = pk2(y4.y, y4.y);
            #pragma unroll
            for (int m = 0; m < 8; m++) ffma2(acc2[8 + m],  ar[m], yd);
            yd = pk2(y4.z, y4.z);
            #pragma unroll
            for (int m = 0; m < 8; m++) ffma2(acc2[16 + m], ar[m], yd);
            yd = pk2(y4.w, y4.w);
            #pragma unroll
            for (int m = 0; m < 8; m++) ffma2(acc2[24 + m], ar[m], yd);
        }

        // ---- h1 = relu(acc2 + b1); part[m] = packed rows: sum_c h1 * W2[col]
        ull part[8];
        #pragma unroll
        for (int m = 0; m < 8; m++) part[m] = 0ull;
        {
            float4 b1v = __ldg(reinterpret_cast<const float4*>(B1) + lane);
            float4 w2v = __ldg(reinterpret_cast<const float4*>(W2) + lane);
            float bc[4] = {b1v.x, b1v.y, b1v.z, b1v.w};
            float wc[4] = {w2v.x, w2v.y, w2v.z, w2v.w};
            #pragma unroll
            for (int c = 0; c < 4; c++) {
                ull w2d = pk2(wc[c], wc[c]);
                #pragma unroll
                for (int m = 0; m < 8; m++) {
                    float lo, hi; upk2(acc2[c * 8 + m], lo, hi);
                    lo = fmaxf(lo + bc[c], 0.f);
                    hi = fmaxf(hi + bc[c], 0.f);
                    ffma2(part[m], pk2(lo, hi), w2d);
                }
            }
        }

        // ---- warp-xor reduce over all 32 lanes (sums all 128 hidden cols);
        //      every lane ends with the full y2[0..15]
        #pragma unroll
        for (int off = 16; off > 0; off >>= 1) {
            #pragma unroll
            for (int m = 0; m < 8; m++) {
                ull o = __shfl_xor_sync(0xffffffffu, part[m], off);
                add2(part[m], o);
            }
        }

        // ---- out[i] = b2 + sum_j A[i][j] * y2[j]  (y2 in registers)
        if (lane < NNODE) {
            float y2[16];
            #pragma unroll
            for (int m = 0; m < 8; m++) upk2(part[m], y2[2 * m], y2[2 * m + 1]);
            float o = __ldg(B2);
            #pragma unroll
            for (int j = 0; j < NNODE; j++)
                o = fmaf(S.A[j][lane], y2[j], o);   // conflict-free
            out[(size_t)q * BSZ * NNODE + (size_t)g * NNODE + lane] = o;
        }
        __syncwarp();   // before next head overwrites HsY
    }
}

extern "C" void kernel_launch(void* const* d_in, const int* in_sizes, int n_in,
                              void* d_out, int out_size)
{
    (void)in_sizes; (void)n_in; (void)out_size;
    // Pin the smem/L1 split: ~70% smem (158KB) leaves ~64KB L1D so W1 (64KB)
    // stays L1-resident during GEMM1. Attribute set is idempotent & capture-safe.
    cudaFuncSetAttribute(gcn_fused5,
                         cudaFuncAttributePreferredSharedMemoryCarveout, 70);
    gcn_fused5<<<BSZ / GPB, NTH>>>(
        (const float*)d_in[0],  (const float*)d_in[1],
        (const float*)d_in[2],  (const float*)d_in[3],
        (const float*)d_in[4],  (const float*)d_in[5],
        (const float*)d_in[6],  (const float*)d_in[7],
        (const float*)d_in[8],  (const float*)d_in[9],
        (const float*)d_in[10], (const float*)d_in[11],
        (const float*)d_in[12], (const float*)d_in[13],
        (float*)d_out);
}